// round 15
// baseline (speedup 1.0000x reference)
#include <cuda_runtime.h>
#include <cuda_bf16.h>
#include <cstdint>

#define TT 10
#define BB 4
#define CCH 256
#define NPIX 256
#define HIDN 1024
#define TRJ 40
#define EPSF 1e-5f

typedef unsigned long long u64;
typedef __nv_bfloat16 bf16;

#define FMA2(d,a,b)    asm("fma.rn.f32x2 %0, %1, %2, %0;" : "+l"(d) : "l"(a), "l"(b))
#define PACK2(d,lo,hi) asm("mov.b64 %0, {%1, %2};" : "=l"(d) : "f"(lo), "f"(hi))
#define UNPACK2(lo,hi,s) asm("mov.b64 {%0, %1}, %2;" : "=f"(lo), "=f"(hi) : "l"(s))

#define BR_STRIDE_A  2621440

// ---------------- mma.sync helpers ----------------
__device__ __forceinline__ uint32_t smem_to_u32(const void* p) {
    uint32_t a;
    asm("{ .reg .u64 t; cvta.to.shared.u64 t, %1; cvt.u32.u64 %0, t; }" : "=r"(a) : "l"(p));
    return a;
}
#define LDSM4(r, addr) \
    asm volatile("ldmatrix.sync.aligned.m8n8.x4.shared.b16 {%0,%1,%2,%3}, [%4];" \
        : "=r"((r)[0]), "=r"((r)[1]), "=r"((r)[2]), "=r"((r)[3]) : "r"(addr))
#define MMA16816(c, a, b0v, b1v) \
    asm volatile("mma.sync.aligned.m16n8k16.row.col.f32.bf16.bf16.f32 " \
        "{%0,%1,%2,%3}, {%4,%5,%6,%7}, {%8,%9}, {%0,%1,%2,%3};" \
        : "+f"((c)[0]), "+f"((c)[1]), "+f"((c)[2]), "+f"((c)[3]) \
        : "r"((a)[0]), "r"((a)[1]), "r"((a)[2]), "r"((a)[3]), "r"(b0v), "r"(b1v))

// ---------------- scratch ----------------
__device__ float g_A  [3*TT*BB*CCH*NPIX];
__device__ u64   g_M  [3*BB*CCH*NPIX];
__device__ unsigned g_QKVb[3*TT*BB*CCH*8];   // spike bitmasks [br][(t*4+b)][c][w]
__device__ float g_P  [TT*BB*CCH*NPIX];
__device__ float g_H  [TT*BB*CCH*NPIX];
__device__ float g_F1 [TT*BB*HIDN*NPIX];
__device__ float g_F2 [TT*BB*CCH*NPIX];
__device__ float g_WupT[270*40];
__device__ float g_bn1s[40], g_bn1o[40];
// bf16 limbs
__device__ bf16 g_Wq_h[196608], g_Wq_m[196608], g_Wq_l[196608];
__device__ bf16 g_Wp_h[65536],  g_Wp_m[65536],  g_Wp_l[65536];
__device__ bf16 g_W1_h[262144], g_W1_m[262144], g_W1_l[262144];
__device__ bf16 g_W2_h[262144], g_W2_m[262144], g_W2_l[262144];
__device__ bf16 g_Xt_h[2621440], g_Xt_m[2621440], g_Xt_l[2621440];
__device__ bf16 g_Ht_h[2621440], g_Ht_m[2621440], g_Ht_l[2621440];
__device__ bf16 g_SpOt[2621440];     // binary, [g][n][256]
__device__ bf16 g_S2t[10485760];     // binary, [g][n][1024]

__device__ __forceinline__ void split3(float v, bf16& h, bf16& m, bf16& l) {
    h = __float2bfloat16(v);
    float r1 = v - __bfloat162float(h);
    m = __float2bfloat16(r1);
    l = __float2bfloat16(r1 - __bfloat162float(m));
}

// ---------------- prep ----------------
__global__ void prep_kernel(const float* __restrict__ up_w, const float* __restrict__ bn1) {
    for (int idx = blockIdx.x*blockDim.x + threadIdx.x; idx < 10800;
         idx += gridDim.x*blockDim.x) {
        int j = idx / 270, r = idx % 270;
        g_WupT[r*40 + j] = up_w[idx];
    }
    int i = blockIdx.x*blockDim.x + threadIdx.x;
    if (i < 40) {
        float gm = bn1[i], bt = bn1[40+i], mu = bn1[80+i], vr = bn1[120+i];
        float s = gm * rsqrtf(vr + EPSF);
        g_bn1s[i] = s; g_bn1o[i] = bt - mu*s;
    }
}

__global__ void prep_w_kernel(const float* __restrict__ q_w, const float* __restrict__ k_w,
                              const float* __restrict__ v_w, const float* __restrict__ proj_w,
                              const float* __restrict__ fc1_w, const float* __restrict__ fc2_w) {
    int i = blockIdx.x*256 + threadIdx.x;
    if (i >= 786432) return;
    float v; bf16 *dh, *dm, *dl; int o;
    if (i < 196608) {
        int br = i >> 16;
        const float* w = (br == 0) ? q_w : ((br == 1) ? k_w : v_w);
        v = w[i & 65535]; o = i; dh = g_Wq_h; dm = g_Wq_m; dl = g_Wq_l;
    } else if (i < 262144) {
        o = i - 196608; v = proj_w[o]; dh = g_Wp_h; dm = g_Wp_m; dl = g_Wp_l;
    } else if (i < 524288) {
        o = i - 262144; v = fc1_w[o]; dh = g_W1_h; dm = g_W1_m; dl = g_W1_l;
    } else {
        o = i - 524288; v = fc2_w[o]; dh = g_W2_h; dm = g_W2_m; dl = g_W2_l;
    }
    bf16 h, m, l; split3(v, h, m, l);
    dh[o] = h; dm[o] = m; dl[o] = l;
}

// float [g][256][256] -> transposed 3-limb bf16 [g][n][256]
__global__ void cvt_xt_kernel(const float* __restrict__ X, bf16* __restrict__ Xh,
                              bf16* __restrict__ Xm, bf16* __restrict__ Xl) {
    __shared__ float s[32][33];
    const int c0 = blockIdx.x*32, n0 = blockIdx.y*32, g = blockIdx.z;
    const int tid = threadIdx.x;
    #pragma unroll
    for (int it = 0; it < 4; it++) {
        int c = (tid>>5) + it*8;
        s[c][tid&31] = X[((size_t)g*256 + c0+c)*256 + n0 + (tid&31)];
    }
    __syncthreads();
    const int cc = tid & 31;
    #pragma unroll
    for (int it = 0; it < 4; it++) {
        int nn = (tid>>5) + it*8;
        bf16 h, m, l; split3(s[cc][nn], h, m, l);
        size_t o = ((size_t)g*256 + n0+nn)*256 + c0+cc;
        Xh[o] = h; Xm[o] = m; Xl[o] = l;
    }
}

// LIF over t + transpose to binary bf16 [g][n][C]  (used for fc1 spikes)
__global__ void lif_t_bf16_kernel(const float* __restrict__ in, bf16* __restrict__ out,
                                  int C, float vth) {
    __shared__ float s[10][32][33];
    const int c0 = blockIdx.x*32, n0 = blockIdx.y*32, b = blockIdx.z;
    const int tid = threadIdx.x;
    for (int t = 0; t < 10; t++)
        #pragma unroll
        for (int it = 0; it < 4; it++) {
            int c = (tid>>5) + it*8;
            s[t][c][tid&31] = in[((size_t)(t*4+b)*C + c0+c)*256 + n0 + (tid&31)];
        }
    __syncthreads();
    const int cc = tid & 31;
    #pragma unroll
    for (int pass = 0; pass < 4; pass++) {
        int nn = (tid>>5) + pass*8;
        float memv = 0.f;
        #pragma unroll
        for (int t = 0; t < 10; t++) {
            float x = s[t][cc][nn];
            memv += 0.5f*(x - memv);
            float sp = memv > vth ? 1.f : 0.f;
            out[((size_t)(t*4+b)*256 + n0+nn)*C + c0+cc] = __float2bfloat16(sp);
            if (sp > 0.f) memv = 0.f;
        }
    }
}

// ---------------- fused: LIF(P) + residual H = x + spike + 3-limb transpose ------------
// grid (8 c-tiles, 8 n-tiles, b=4), 256 threads.
__global__ void lif_cvt_kernel(const float* __restrict__ P, const float* __restrict__ X,
                               float* __restrict__ H, bf16* __restrict__ Hh,
                               bf16* __restrict__ Hm, bf16* __restrict__ Hl) {
    __shared__ float s[10][32][33];
    const int c0 = blockIdx.x*32, n0 = blockIdx.y*32, b = blockIdx.z;
    const int tid = threadIdx.x;
    // phase 1: load P tiles
    for (int t = 0; t < 10; t++)
        #pragma unroll
        for (int it = 0; it < 4; it++) {
            int c = (tid>>5) + it*8;
            s[t][c][tid&31] = P[((size_t)(t*4+b)*256 + c0+c)*256 + n0 + (tid&31)];
        }
    __syncthreads();
    // phase 2: LIF scan per (c,n), overwrite s with spikes
    {
        const int cc = tid & 31;
        #pragma unroll
        for (int pass = 0; pass < 4; pass++) {
            int nn = (tid>>5) + pass*8;
            float memv = 0.f;
            #pragma unroll
            for (int t = 0; t < 10; t++) {
                float x = s[t][cc][nn];
                memv += 0.5f*(x - memv);
                float sp = memv > 1.0f ? 1.f : 0.f;
                s[t][cc][nn] = sp;
                if (sp > 0.f) memv = 0.f;
            }
        }
    }
    __syncthreads();
    // phase 3a: H = x + spike (coalesced in n), overwrite s with h
    for (int t = 0; t < 10; t++)
        #pragma unroll
        for (int it = 0; it < 4; it++) {
            int c = (tid>>5) + it*8;
            size_t off = ((size_t)(t*4+b)*256 + c0+c)*256 + n0 + (tid&31);
            float h = X[off] + s[t][c][tid&31];
            H[off] = h;
            s[t][c][tid&31] = h;
        }
    __syncthreads();
    // phase 3b: limb split, transposed write (coalesced in c)
    {
        const int cc = tid & 31;
        for (int t = 0; t < 10; t++)
            #pragma unroll
            for (int pass = 0; pass < 4; pass++) {
                int nn = (tid>>5) + pass*8;
                bf16 h, m, l; split3(s[t][cc][nn], h, m, l);
                size_t o = ((size_t)(t*4+b)*256 + n0+nn)*256 + c0+cc;
                Hh[o] = h; Hm[o] = m; Hl[o] = l;
            }
    }
}

// ---------------- mma.sync GEMM + BN(+bias), limb-decomposed ----------------------------
template<int CIN, int NB>
__global__ void __launch_bounds__(256, 3) gemm_mma_kernel(
        const bf16* __restrict__ Xh, const bf16* __restrict__ Xm, const bf16* __restrict__ Xl,
        const bf16* __restrict__ Wh, const bf16* __restrict__ Wm, const bf16* __restrict__ Wl,
        const float* __restrict__ B0, const float* __restrict__ B1, const float* __restrict__ B2,
        const float* __restrict__ bias, float* __restrict__ Y, int Cout) {
    extern __shared__ char dsm[];
    const int z = blockIdx.z, br = z/40, g = z - br*40;
    const int mo = blockIdx.y*128, no = blockIdx.x*64;
    const int tid = threadIdx.x, wid = tid>>5, lane = tid&31;
    const bf16* Wp[3] = {Wh + (size_t)br*Cout*CIN, Wm + (size_t)br*Cout*CIN,
                         Wl + (size_t)br*Cout*CIN};
    const bf16* Xp[3];
    Xp[0] = Xh + (size_t)g*256*CIN;
    Xp[1] = (NB > 1) ? Xm + (size_t)g*256*CIN : Xp[0];
    Xp[2] = (NB > 1) ? Xl + (size_t)g*256*CIN : Xp[0];

    float acc[8][4];
    #pragma unroll
    for (int j = 0; j < 8; j++)
        #pragma unroll
        for (int i = 0; i < 4; i++) acc[j][i] = 0.f;

    const uint32_t sbase = smem_to_u32(dsm);
    const int rowA = wid*16 + (lane & 7) + ((lane & 8) ? 8 : 0);
    const int h16A = (lane & 16) ? 16 : 0;
    const int axor = (rowA & 7)*16;
    const uint32_t aoff = sbase + rowA*128;
    const int rB = (lane & 7) + ((lane & 16) ? 8 : 0);
    const int h16B = (lane & 8) ? 16 : 0;
    const int bxor = (lane & 7)*16;
    const uint32_t boff = sbase + 49152 + rB*128;

    for (int ch = 0; ch < CIN/64; ch++) {
        #pragma unroll
        for (int l = 0; l < 3; l++) {
            #pragma unroll
            for (int it = 0; it < 4; it++) {
                int q = tid + it*256;
                int row = q >> 3, c16 = q & 7;
                uint4 v = *reinterpret_cast<const uint4*>(
                    &Wp[l][(size_t)(mo+row)*CIN + ch*64 + c16*8]);
                *reinterpret_cast<uint4*>(dsm + l*16384 + row*128 +
                                          ((c16*16) ^ ((row & 7)*16))) = v;
            }
        }
        #pragma unroll
        for (int l = 0; l < NB; l++) {
            #pragma unroll
            for (int it = 0; it < 2; it++) {
                int q = tid + it*256;
                int row = q >> 3, c16 = q & 7;
                uint4 v = *reinterpret_cast<const uint4*>(
                    &Xp[l][(size_t)(no+row)*CIN + ch*64 + c16*8]);
                *reinterpret_cast<uint4*>(dsm + 49152 + l*8192 + row*128 +
                                          ((c16*16) ^ ((row & 7)*16))) = v;
            }
        }
        __syncthreads();
        #pragma unroll
        for (int ks = 0; ks < 4; ks++) {
            uint32_t af[3][4];
            #pragma unroll
            for (int la = 0; la < 3; la++)
                LDSM4(af[la], aoff + la*16384 + ((ks*32 + h16A) ^ axor));
            #pragma unroll
            for (int j = 0; j < 4; j++) {
                #pragma unroll
                for (int lb = 0; lb < NB; lb++) {
                    uint32_t bf4[4];
                    LDSM4(bf4, boff + lb*8192 + j*2048 + ((ks*32 + h16B) ^ bxor));
                    const int lamax = (NB == 3) ? (3 - lb) : 3;
                    #pragma unroll
                    for (int la = 0; la < 3; la++) {
                        if (la < lamax) {
                            MMA16816(acc[2*j],   af[la], bf4[0], bf4[1]);
                            MMA16816(acc[2*j+1], af[la], bf4[2], bf4[3]);
                        }
                    }
                }
            }
        }
        __syncthreads();
    }
    const float* bnp = (br == 0) ? B0 : ((br == 1) ? B1 : B2);
    const int g4 = lane >> 2, tg = lane & 3;
    const int o0 = mo + wid*16 + g4, o1 = o0 + 8;
    float gm0 = bnp[o0], bt0 = bnp[Cout+o0], mu0 = bnp[2*Cout+o0], vr0 = bnp[3*Cout+o0];
    float s0 = gm0 * rsqrtf(vr0 + EPSF);
    float f0 = bt0 - mu0*s0 + (bias ? s0*bias[o0] : 0.f);
    float gm1 = bnp[o1], bt1 = bnp[Cout+o1], mu1 = bnp[2*Cout+o1], vr1 = bnp[3*Cout+o1];
    float s1 = gm1 * rsqrtf(vr1 + EPSF);
    float f1 = bt1 - mu1*s1 + (bias ? s1*bias[o1] : 0.f);
    float* Yb = Y + ((size_t)(br*40 + g)*Cout)*256;
    #pragma unroll
    for (int j = 0; j < 8; j++) {
        int col = no + j*8 + tg*2;
        float2 r0; r0.x = s0*acc[j][0] + f0; r0.y = s0*acc[j][1] + f0;
        *reinterpret_cast<float2*>(&Yb[(size_t)o0*256 + col]) = r0;
        float2 r1; r1.x = s1*acc[j][2] + f1; r1.y = s1*acc[j][3] + f1;
        *reinterpret_cast<float2*>(&Yb[(size_t)o1*256 + col]) = r1;
    }
}

// ---------------- TIM up-conv + bn1 + LIF1 -> 40-bit masks ------------------------------
__global__ void upconv_lif_kernel(const float* __restrict__ A, u64* __restrict__ M) {
    extern __shared__ __align__(16) float sm[];
    float* As  = sm;
    float* Wsm = sm + 9720;
    const int c = blockIdx.x, b = blockIdx.y, br = blockIdx.z;
    const float* Ab = A + (size_t)br * BR_STRIDE_A;
    const int tid = threadIdx.x;
    for (int i = tid; i < 10800; i += 256) Wsm[i] = g_WupT[i];
    for (int idx = tid; idx < 9720; idx += 256) {
        int t = idx / 972, q = idx % 972;
        int dc = q / 324, q2 = q % 324;
        int hh = q2 / 18, ww = q2 % 18;
        int cc = c - 1 + dc;
        float v = 0.f;
        if (cc >= 0 && cc < 256 && hh >= 1 && hh <= 16 && ww >= 1 && ww <= 16)
            v = Ab[((t*4 + b)*256 + cc)*256 + (hh-1)*16 + (ww-1)];
        As[idx] = v;
    }
    __syncthreads();
    const int h = tid >> 4, w = tid & 15;
    u64 acc[20];
    #pragma unroll
    for (int j = 0; j < 20; j++) acc[j] = 0ull;
    for (int t = 0; t < 10; t++) {
        const float* at = As + t*972 + h*18 + w;
        const u64* wt = reinterpret_cast<const u64*>(Wsm) + t*540;
        #pragma unroll
        for (int dc = 0; dc < 3; dc++)
            #pragma unroll
            for (int dh = 0; dh < 3; dh++)
                #pragma unroll
                for (int dw = 0; dw < 3; dw++) {
                    float a = at[dc*324 + dh*18 + dw];
                    u64 a2; PACK2(a2, a, a);
                    const ulonglong2* wp2 =
                        reinterpret_cast<const ulonglong2*>(wt + (dc*9 + dh*3 + dw)*20);
                    #pragma unroll
                    for (int j2 = 0; j2 < 10; j2++) {
                        ulonglong2 wv = wp2[j2];
                        FMA2(acc[2*j2  ], a2, wv.x);
                        FMA2(acc[2*j2+1], a2, wv.y);
                    }
                }
    }
    float av[40];
    #pragma unroll
    for (int p = 0; p < 20; p++) {
        float lo, hi; UNPACK2(lo, hi, acc[p]);
        av[2*p] = lo; av[2*p+1] = hi;
    }
    u64 mask = 0ull;
    #pragma unroll
    for (int q = 0; q < 4; q++) {
        float memv = 0.f;
        #pragma unroll
        for (int s = 0; s < 10; s++) {
            int j = 4*s + q;
            float x = g_bn1s[j]*av[j] + g_bn1o[j];
            memv += 0.5f*(x - memv);
            if (memv > 1.0f) { mask |= (1ull << j); memv = 0.f; }
        }
    }
    M[((size_t)(br*4 + b)*256 + c)*256 + tid] = mask;
}

// ---------------- TIM down-conv nibble-LUT + bn2 + LIF2 -> spike BITMASKS ---------------
__global__ void downconv_lif_kernel(const u64* __restrict__ Mg, const float* __restrict__ Wd_g,
                                    const float* __restrict__ bn2, unsigned* __restrict__ Bits) {
    const int c = blockIdx.x, b = blockIdx.y, br = blockIdx.z;
    const u64* Mb = Mg + (size_t)(br*4 + b)*65536;
    __shared__ __align__(16) u64 Ms[972];
    __shared__ float LUT[4320];
    __shared__ float s_sc[10], s_of[10];
    const int tid = threadIdx.x;
    for (int i = tid; i < 4320; i += 256) {
        int tap = i / 160, rem = i - tap*160;
        int t = rem >> 4, nib = rem & 15;
        float v = 0.f;
        if (nib & 1) v += Wd_g[t*108 +  0 + tap];
        if (nib & 2) v += Wd_g[t*108 + 27 + tap];
        if (nib & 4) v += Wd_g[t*108 + 54 + tap];
        if (nib & 8) v += Wd_g[t*108 + 81 + tap];
        LUT[i] = v;
    }
    if (tid < 10) {
        float gm = bn2[tid], bt = bn2[10+tid], mu = bn2[20+tid], vr = bn2[30+tid];
        float s = gm * rsqrtf(vr + EPSF);
        s_sc[tid] = s; s_of[tid] = bt - mu*s;
    }
    for (int i = tid; i < 972; i += 256) {
        int dc = i / 324, rem = i - dc*324;
        int hh = rem / 18, ww = rem - hh*18;
        int cc = c - 1 + dc;
        u64 m = 0ull;
        if (cc >= 0 && cc < 256 && hh >= 1 && hh <= 16 && ww >= 1 && ww <= 16)
            m = Mb[cc*256 + (hh-1)*16 + (ww-1)];
        Ms[i] = m;
    }
    __syncthreads();
    const int h = tid >> 4, w = tid & 15;
    float acc[10];
    #pragma unroll
    for (int t = 0; t < 10; t++) acc[t] = 0.f;
    #pragma unroll
    for (int dc = 0; dc < 3; dc++)
        #pragma unroll
        for (int dh = 0; dh < 3; dh++)
            #pragma unroll
            for (int dw = 0; dw < 3; dw++) {
                u64 m = Ms[dc*324 + (h+dh)*18 + (w+dw)];
                unsigned mlo = (unsigned)m, mhi = (unsigned)(m >> 32);
                const float* lt = LUT + (dc*9 + dh*3 + dw)*160;
                #pragma unroll
                for (int t = 0; t < 8; t++)
                    acc[t] += lt[t*16 + ((mlo >> (4*t)) & 15u)];
                acc[8] += lt[128 + (mhi & 15u)];
                acc[9] += lt[144 + ((mhi >> 4) & 15u)];
            }
    const int wid = tid >> 5, lane = tid & 31;
    float memv = 0.f;
    #pragma unroll
    for (int t = 0; t < 10; t++) {
        float x = s_sc[t]*acc[t] + s_of[t];
        memv += 0.5f*(x - memv);
        float sp = memv > 1.0f ? 1.f : 0.f;
        unsigned blt = __ballot_sync(0xffffffffu, sp > 0.f);
        if (lane == 0)
            Bits[br*81920 + ((t*4 + b)*256 + c)*8 + wid] = blt;
        if (sp > 0.f) memv = 0.f;
    }
}

// ---------------- fused attention (popc, exact) + attn-LIF -> binary bf16 transposed ----
// grid (h=16, b=4), 256 threads, t-loop inside; membrane per (n, 16 d) in registers.
__global__ void attn_lif_kernel(const unsigned* __restrict__ Bits, bf16* __restrict__ SpOt) {
    const int hh = blockIdx.x, b = blockIdx.y;
    __shared__ unsigned Qsb[16][8], Ksb[16][8], Vsb[16][8];
    __shared__ __align__(16) float Gs[16][16];
    const int tid = threadIdx.x;
    const int n = tid;
    const int word = n >> 5;
    const unsigned bit = 1u << (n & 31);
    u64 one2; PACK2(one2, 1.0f, 1.0f);
    float memv[16];
    #pragma unroll
    for (int d = 0; d < 16; d++) memv[d] = 0.f;

    for (int t = 0; t < 10; t++) {
        const int gbase = ((t*4 + b)*256 + hh*16)*8;
        if (tid < 128) {
            int d = tid >> 3, w = tid & 7;
            Qsb[d][w] = Bits[gbase + d*8 + w];
            Ksb[d][w] = Bits[81920 + gbase + d*8 + w];
        } else {
            int r = tid - 128;
            int d = r >> 3, w = r & 7;
            Vsb[d][w] = Bits[163840 + gbase + d*8 + w];
        }
        __syncthreads();
        {   // G[d1][d2] = popc(K & V)
            int d1 = tid >> 4, d2 = tid & 15;
            unsigned s = 0;
            #pragma unroll
            for (int w = 0; w < 8; w++)
                s += __popc(Ksb[d1][w] & Vsb[d2][w]);
            Gs[d1][d2] = (float)s;
        }
        __syncthreads();
        u64 acc2[8];
        #pragma unroll
        for (int i = 0; i < 8; i++) acc2[i] = 0ull;
        #pragma unroll
        for (int d1 = 0; d1 < 16; d1++) {
            if (Qsb[d1][word] & bit) {
                const u64* gp = reinterpret_cast<const u64*>(&Gs[d1][0]);
                #pragma unroll
                for (int i = 0; i < 8; i++) FMA2(acc2[i], one2, gp[i]);
            }
        }
        // LIF vth=0.5 + transposed bf16 write (16 contiguous bf16 per thread)
        bf16 spv[16];
        #pragma unroll
        for (int i = 0; i < 8; i++) {
            float lo, hi; UNPACK2(lo, hi, acc2[i]);
            float xa = 0.25f*lo, xb = 0.25f*hi;
            int da = 2*i, db = 2*i+1;
            float ma = memv[da] + 0.5f*(xa - memv[da]);
            float sa = ma > 0.5f ? 1.f : 0.f;
            memv[da] = (sa > 0.f) ? 0.f : ma;
            spv[da] = __float2bfloat16(sa);
            float mb = memv[db] + 0.5f*(xb - memv[db]);
            float sb = mb > 0.5f ? 1.f : 0.f;
            memv[db] = (sb > 0.f) ? 0.f : mb;
            spv[db] = __float2bfloat16(sb);
        }
        bf16* op = &SpOt[((size_t)(t*4 + b)*256 + n)*256 + hh*16];
        *reinterpret_cast<uint4*>(op)     = *reinterpret_cast<uint4*>(&spv[0]);
        *reinterpret_cast<uint4*>(op + 8) = *reinterpret_cast<uint4*>(&spv[8]);
        __syncthreads();
    }
}

// ---------------- float LIF over t ------------------------------------------------------
__global__ void lif_std_kernel(const float* __restrict__ in, float* __restrict__ out,
                               const float* __restrict__ res, int Cch, float vth) {
    int idx = blockIdx.x*256 + threadIdx.x;
    int per_b = Cch*256;
    int b = idx / per_b, cn = idx - b*per_b;
    float mem = 0.f;
    #pragma unroll
    for (int t = 0; t < 10; t++) {
        int off = (t*4 + b)*per_b + cn;
        float x = in[off];
        mem += 0.5f*(x - mem);
        float sp = mem > vth ? 1.f : 0.f;
        out[off] = res ? res[off] + sp : sp;
        if (sp > 0.f) mem = 0.f;
    }
}

// ---------------- launch ----------------
extern "C" void kernel_launch(void* const* d_in, const int* in_sizes, int n_in,
                              void* d_out, int out_size) {
    const float* x        = (const float*)d_in[0];
    const float* q_w      = (const float*)d_in[1];
    const float* q_bn     = (const float*)d_in[2];
    const float* k_w      = (const float*)d_in[3];
    const float* k_bn     = (const float*)d_in[4];
    const float* v_w      = (const float*)d_in[5];
    const float* v_bn     = (const float*)d_in[6];
    const float* proj_w   = (const float*)d_in[7];
    const float* proj_bn  = (const float*)d_in[8];
    const float* tim_up_w = (const float*)d_in[9];
    const float* tim_bn1  = (const float*)d_in[10];
    const float* tim_dn_w = (const float*)d_in[11];
    const float* tim_bn2  = (const float*)d_in[12];
    const float* fc1_w    = (const float*)d_in[13];
    const float* fc1_b    = (const float*)d_in[14];
    const float* fc1_bn   = (const float*)d_in[15];
    const float* fc2_w    = (const float*)d_in[16];
    const float* fc2_b    = (const float*)d_in[17];
    const float* fc2_bn   = (const float*)d_in[18];
    float* out = (float*)d_out;

    float *bA,*bP,*bH,*bF1,*bF2;
    u64 *bM;
    unsigned *bQKVb;
    bf16 *bXh,*bXm,*bXl,*bHh,*bHm,*bHl,*bSpOt,*bS2t;
    bf16 *wqh,*wqm,*wql,*wph,*wpm,*wpl,*w1h,*w1m,*w1l,*w2h,*w2m,*w2l;
    cudaGetSymbolAddress((void**)&bA,    g_A);
    cudaGetSymbolAddress((void**)&bM,    g_M);
    cudaGetSymbolAddress((void**)&bQKVb, g_QKVb);
    cudaGetSymbolAddress((void**)&bP,    g_P);
    cudaGetSymbolAddress((void**)&bH,    g_H);
    cudaGetSymbolAddress((void**)&bF1,   g_F1);
    cudaGetSymbolAddress((void**)&bF2,   g_F2);
    cudaGetSymbolAddress((void**)&bXh, g_Xt_h); cudaGetSymbolAddress((void**)&bXm, g_Xt_m);
    cudaGetSymbolAddress((void**)&bXl, g_Xt_l);
    cudaGetSymbolAddress((void**)&bHh, g_Ht_h); cudaGetSymbolAddress((void**)&bHm, g_Ht_m);
    cudaGetSymbolAddress((void**)&bHl, g_Ht_l);
    cudaGetSymbolAddress((void**)&bSpOt, g_SpOt);
    cudaGetSymbolAddress((void**)&bS2t,  g_S2t);
    cudaGetSymbolAddress((void**)&wqh, g_Wq_h); cudaGetSymbolAddress((void**)&wqm, g_Wq_m);
    cudaGetSymbolAddress((void**)&wql, g_Wq_l);
    cudaGetSymbolAddress((void**)&wph, g_Wp_h); cudaGetSymbolAddress((void**)&wpm, g_Wp_m);
    cudaGetSymbolAddress((void**)&wpl, g_Wp_l);
    cudaGetSymbolAddress((void**)&w1h, g_W1_h); cudaGetSymbolAddress((void**)&w1m, g_W1_m);
    cudaGetSymbolAddress((void**)&w1l, g_W1_l);
    cudaGetSymbolAddress((void**)&w2h, g_W2_h); cudaGetSymbolAddress((void**)&w2m, g_W2_m);
    cudaGetSymbolAddress((void**)&w2l, g_W2_l);

    const int SM6 = 73728;   // A 48KB + B 24KB
    const int SM1 = 57344;   // A 48KB + B 8KB
    cudaFuncSetAttribute(upconv_lif_kernel, cudaFuncAttributeMaxDynamicSharedMemorySize, 82080);
    cudaFuncSetAttribute(gemm_mma_kernel<256,3>,  cudaFuncAttributeMaxDynamicSharedMemorySize, SM6);
    cudaFuncSetAttribute(gemm_mma_kernel<256,1>,  cudaFuncAttributeMaxDynamicSharedMemorySize, SM1);
    cudaFuncSetAttribute(gemm_mma_kernel<1024,1>, cudaFuncAttributeMaxDynamicSharedMemorySize, SM1);

    prep_kernel<<<43, 256>>>(tim_up_w, tim_bn1);
    prep_w_kernel<<<3072, 256>>>(q_w, k_w, v_w, proj_w, fc1_w, fc2_w);

    // --- qkv (mma.sync) -> TIM pipeline -> spike bitmasks ---
    cvt_xt_kernel<<<dim3(8,8,40), 256>>>(x, bXh, bXm, bXl);
    gemm_mma_kernel<256,3><<<dim3(4,2,120), 256, SM6>>>(
        bXh, bXm, bXl, wqh, wqm, wql, q_bn, k_bn, v_bn, nullptr, bA, 256);
    upconv_lif_kernel<<<dim3(256,4,3), 256, 82080>>>(bA, bM);
    downconv_lif_kernel<<<dim3(256,4,3), 256>>>(bM, tim_dn_w, tim_bn2, bQKVb);

    // --- fused attention + attn-LIF (binary bf16 transposed) ---
    attn_lif_kernel<<<dim3(16,4), 256>>>(bQKVb, bSpOt);

    // --- proj (binary X) -> fused LIF + residual + limb split ---
    gemm_mma_kernel<256,1><<<dim3(4,2,40), 256, SM1>>>(
        bSpOt, nullptr, nullptr, wph, wpm, wpl, proj_bn, proj_bn, proj_bn, nullptr, bP, 256);
    lif_cvt_kernel<<<dim3(8,8,4), 256>>>(bP, x, bH, bHh, bHm, bHl);

    // --- mlp ---
    gemm_mma_kernel<256,3><<<dim3(4,8,40), 256, SM6>>>(
        bHh, bHm, bHl, w1h, w1m, w1l, fc1_bn, fc1_bn, fc1_bn, fc1_b, bF1, 1024);
    lif_t_bf16_kernel<<<dim3(32,8,4), 256>>>(bF1, bS2t, 1024, 1.0f);
    gemm_mma_kernel<1024,1><<<dim3(4,2,40), 256, SM1>>>(
        bS2t, nullptr, nullptr, w2h, w2m, w2l, fc2_bn, fc2_bn, fc2_bn, fc2_b, bF2, 256);
    lif_std_kernel<<<1024, 256>>>(bF2, out, bH, 256, 1.0f);
}

// round 16
// speedup vs baseline: 1.0235x; 1.0235x over previous
#include <cuda_runtime.h>
#include <cuda_bf16.h>
#include <cstdint>

#define TT 10
#define BB 4
#define CCH 256
#define NPIX 256
#define HIDN 1024
#define TRJ 40
#define EPSF 1e-5f

typedef unsigned long long u64;
typedef __nv_bfloat16 bf16;

#define FMA2(d,a,b)    asm("fma.rn.f32x2 %0, %1, %2, %0;" : "+l"(d) : "l"(a), "l"(b))
#define PACK2(d,lo,hi) asm("mov.b64 %0, {%1, %2};" : "=l"(d) : "f"(lo), "f"(hi))
#define UNPACK2(lo,hi,s) asm("mov.b64 {%0, %1}, %2;" : "=f"(lo), "=f"(hi) : "l"(s))

#define BR_STRIDE_A  2621440

// ---------------- mma.sync helpers ----------------
__device__ __forceinline__ uint32_t smem_to_u32(const void* p) {
    uint32_t a;
    asm("{ .reg .u64 t; cvta.to.shared.u64 t, %1; cvt.u32.u64 %0, t; }" : "=r"(a) : "l"(p));
    return a;
}
#define LDSM4(r, addr) \
    asm volatile("ldmatrix.sync.aligned.m8n8.x4.shared.b16 {%0,%1,%2,%3}, [%4];" \
        : "=r"((r)[0]), "=r"((r)[1]), "=r"((r)[2]), "=r"((r)[3]) : "r"(addr))
#define MMA16816(c, a, b0v, b1v) \
    asm volatile("mma.sync.aligned.m16n8k16.row.col.f32.bf16.bf16.f32 " \
        "{%0,%1,%2,%3}, {%4,%5,%6,%7}, {%8,%9}, {%0,%1,%2,%3};" \
        : "+f"((c)[0]), "+f"((c)[1]), "+f"((c)[2]), "+f"((c)[3]) \
        : "r"((a)[0]), "r"((a)[1]), "r"((a)[2]), "r"((a)[3]), "r"(b0v), "r"(b1v))

// ---------------- scratch ----------------
__device__ float g_A  [3*TT*BB*CCH*NPIX];
__device__ u64   g_M  [3*BB*CCH*NPIX];
__device__ unsigned g_QKVb[3*TT*BB*CCH*8];   // spike bitmasks [br][(t*4+b)][c][w]
__device__ float g_O  [TT*BB*CCH*NPIX];
__device__ float g_P  [TT*BB*CCH*NPIX];
__device__ float g_H  [TT*BB*CCH*NPIX];
__device__ float g_F1 [TT*BB*HIDN*NPIX];
__device__ float g_F2 [TT*BB*CCH*NPIX];
__device__ float g_WupT[270*40];
__device__ float g_bn1s[40], g_bn1o[40];
// bf16 limbs
__device__ bf16 g_Wq_h[196608], g_Wq_m[196608], g_Wq_l[196608];
__device__ bf16 g_Wp_h[65536],  g_Wp_m[65536],  g_Wp_l[65536];
__device__ bf16 g_W1_h[262144], g_W1_m[262144], g_W1_l[262144];
__device__ bf16 g_W2_h[262144], g_W2_m[262144], g_W2_l[262144];
__device__ bf16 g_Xt_h[2621440], g_Xt_m[2621440], g_Xt_l[2621440];
__device__ bf16 g_Ht_h[2621440], g_Ht_m[2621440], g_Ht_l[2621440];
__device__ bf16 g_SpOt[2621440];     // binary, [g][n][256]
__device__ bf16 g_S2t[10485760];     // binary, [g][n][1024]

__device__ __forceinline__ void split3(float v, bf16& h, bf16& m, bf16& l) {
    h = __float2bfloat16(v);
    float r1 = v - __bfloat162float(h);
    m = __float2bfloat16(r1);
    l = __float2bfloat16(r1 - __bfloat162float(m));
}

// ---------------- prep ----------------
__global__ void prep_kernel(const float* __restrict__ up_w, const float* __restrict__ bn1) {
    for (int idx = blockIdx.x*blockDim.x + threadIdx.x; idx < 10800;
         idx += gridDim.x*blockDim.x) {
        int j = idx / 270, r = idx % 270;
        g_WupT[r*40 + j] = up_w[idx];
    }
    int i = blockIdx.x*blockDim.x + threadIdx.x;
    if (i < 40) {
        float gm = bn1[i], bt = bn1[40+i], mu = bn1[80+i], vr = bn1[120+i];
        float s = gm * rsqrtf(vr + EPSF);
        g_bn1s[i] = s; g_bn1o[i] = bt - mu*s;
    }
}

__global__ void prep_w_kernel(const float* __restrict__ q_w, const float* __restrict__ k_w,
                              const float* __restrict__ v_w, const float* __restrict__ proj_w,
                              const float* __restrict__ fc1_w, const float* __restrict__ fc2_w) {
    int i = blockIdx.x*256 + threadIdx.x;
    if (i >= 786432) return;
    float v; bf16 *dh, *dm, *dl; int o;
    if (i < 196608) {
        int br = i >> 16;
        const float* w = (br == 0) ? q_w : ((br == 1) ? k_w : v_w);
        v = w[i & 65535]; o = i; dh = g_Wq_h; dm = g_Wq_m; dl = g_Wq_l;
    } else if (i < 262144) {
        o = i - 196608; v = proj_w[o]; dh = g_Wp_h; dm = g_Wp_m; dl = g_Wp_l;
    } else if (i < 524288) {
        o = i - 262144; v = fc1_w[o]; dh = g_W1_h; dm = g_W1_m; dl = g_W1_l;
    } else {
        o = i - 524288; v = fc2_w[o]; dh = g_W2_h; dm = g_W2_m; dl = g_W2_l;
    }
    bf16 h, m, l; split3(v, h, m, l);
    dh[o] = h; dm[o] = m; dl[o] = l;
}

// float [g][256][256] -> transposed 3-limb bf16 [g][n][256]
__global__ void cvt_xt_kernel(const float* __restrict__ X, bf16* __restrict__ Xh,
                              bf16* __restrict__ Xm, bf16* __restrict__ Xl) {
    __shared__ float s[32][33];
    const int c0 = blockIdx.x*32, n0 = blockIdx.y*32, g = blockIdx.z;
    const int tid = threadIdx.x;
    #pragma unroll
    for (int it = 0; it < 4; it++) {
        int c = (tid>>5) + it*8;
        s[c][tid&31] = X[((size_t)g*256 + c0+c)*256 + n0 + (tid&31)];
    }
    __syncthreads();
    const int cc = tid & 31;
    #pragma unroll
    for (int it = 0; it < 4; it++) {
        int nn = (tid>>5) + it*8;
        bf16 h, m, l; split3(s[cc][nn], h, m, l);
        size_t o = ((size_t)g*256 + n0+nn)*256 + c0+cc;
        Xh[o] = h; Xm[o] = m; Xl[o] = l;
    }
}

// LIF over t + transpose to binary bf16 [g][n][C]
__global__ void lif_t_bf16_kernel(const float* __restrict__ in, bf16* __restrict__ out,
                                  int C, float vth) {
    __shared__ float s[10][32][33];
    const int c0 = blockIdx.x*32, n0 = blockIdx.y*32, b = blockIdx.z;
    const int tid = threadIdx.x;
    for (int t = 0; t < 10; t++)
        #pragma unroll
        for (int it = 0; it < 4; it++) {
            int c = (tid>>5) + it*8;
            s[t][c][tid&31] = in[((size_t)(t*4+b)*C + c0+c)*256 + n0 + (tid&31)];
        }
    __syncthreads();
    const int cc = tid & 31;
    #pragma unroll
    for (int pass = 0; pass < 4; pass++) {
        int nn = (tid>>5) + pass*8;
        float memv = 0.f;
        #pragma unroll
        for (int t = 0; t < 10; t++) {
            float x = s[t][cc][nn];
            memv += 0.5f*(x - memv);
            float sp = memv > vth ? 1.f : 0.f;
            out[((size_t)(t*4+b)*256 + n0+nn)*C + c0+cc] = __float2bfloat16(sp);
            if (sp > 0.f) memv = 0.f;
        }
    }
}

// ---------------- mma.sync GEMM + BN(+bias), limb-decomposed, reg-prefetch pipeline ----
// D[mo+m][no+n] = sum_k W[m][k]*X[n][k]. M=128 N=64, K chunks of 64, 8 warps.
template<int CIN, int NB>
__global__ void __launch_bounds__(256, 1) gemm_mma_kernel(
        const bf16* __restrict__ Xh, const bf16* __restrict__ Xm, const bf16* __restrict__ Xl,
        const bf16* __restrict__ Wh, const bf16* __restrict__ Wm, const bf16* __restrict__ Wl,
        const float* __restrict__ B0, const float* __restrict__ B1, const float* __restrict__ B2,
        const float* __restrict__ bias, float* __restrict__ Y, int Cout) {
    extern __shared__ char dsm[];
    const int z = blockIdx.z, br = z/40, g = z - br*40;
    const int mo = blockIdx.y*128, no = blockIdx.x*64;
    const int tid = threadIdx.x, wid = tid>>5, lane = tid&31;
    const bf16* Wp[3] = {Wh + (size_t)br*Cout*CIN, Wm + (size_t)br*Cout*CIN,
                         Wl + (size_t)br*Cout*CIN};
    const bf16* Xp[3];
    Xp[0] = Xh + (size_t)g*256*CIN;
    Xp[1] = (NB > 1) ? Xm + (size_t)g*256*CIN : Xp[0];
    Xp[2] = (NB > 1) ? Xl + (size_t)g*256*CIN : Xp[0];

    float acc[8][4];
    #pragma unroll
    for (int j = 0; j < 8; j++)
        #pragma unroll
        for (int i = 0; i < 4; i++) acc[j][i] = 0.f;

    const uint32_t sbase = smem_to_u32(dsm);
    const int rowA = wid*16 + (lane & 7) + ((lane & 8) ? 8 : 0);
    const int h16A = (lane & 16) ? 16 : 0;
    const int axor = (rowA & 7)*16;
    const uint32_t aoff = sbase + rowA*128;
    const int rB = (lane & 7) + ((lane & 16) ? 8 : 0);
    const int h16B = (lane & 8) ? 16 : 0;
    const int bxor = (lane & 7)*16;
    const uint32_t boff = sbase + 49152 + rB*128;

    const int NCH = CIN/64;
    uint4 pa[12], pb[2*NB];

    // prefetch chunk 0
    #pragma unroll
    for (int it = 0; it < 12; it++) {
        int l = it >> 2, q = tid + (it & 3)*256;
        int row = q >> 3, c16 = q & 7;
        pa[it] = *reinterpret_cast<const uint4*>(&Wp[l][(size_t)(mo+row)*CIN + c16*8]);
    }
    #pragma unroll
    for (int it = 0; it < 2*NB; it++) {
        int l = it >> 1, q = tid + (it & 1)*256;
        int row = q >> 3, c16 = q & 7;
        pb[it] = *reinterpret_cast<const uint4*>(&Xp[l][(size_t)(no+row)*CIN + c16*8]);
    }

    for (int ch = 0; ch < NCH; ch++) {
        // store prefetched regs to swizzled smem
        #pragma unroll
        for (int it = 0; it < 12; it++) {
            int l = it >> 2, q = tid + (it & 3)*256;
            int row = q >> 3, c16 = q & 7;
            *reinterpret_cast<uint4*>(dsm + l*16384 + row*128 +
                                      ((c16*16) ^ ((row & 7)*16))) = pa[it];
        }
        #pragma unroll
        for (int it = 0; it < 2*NB; it++) {
            int l = it >> 1, q = tid + (it & 1)*256;
            int row = q >> 3, c16 = q & 7;
            *reinterpret_cast<uint4*>(dsm + 49152 + l*8192 + row*128 +
                                      ((c16*16) ^ ((row & 7)*16))) = pb[it];
        }
        __syncthreads();
        // prefetch next chunk (LDG latency hides behind MMA below)
        if (ch + 1 < NCH) {
            #pragma unroll
            for (int it = 0; it < 12; it++) {
                int l = it >> 2, q = tid + (it & 3)*256;
                int row = q >> 3, c16 = q & 7;
                pa[it] = *reinterpret_cast<const uint4*>(
                    &Wp[l][(size_t)(mo+row)*CIN + (ch+1)*64 + c16*8]);
            }
            #pragma unroll
            for (int it = 0; it < 2*NB; it++) {
                int l = it >> 1, q = tid + (it & 1)*256;
                int row = q >> 3, c16 = q & 7;
                pb[it] = *reinterpret_cast<const uint4*>(
                    &Xp[l][(size_t)(no+row)*CIN + (ch+1)*64 + c16*8]);
            }
        }
        // compute on current chunk
        #pragma unroll
        for (int ks = 0; ks < 4; ks++) {
            uint32_t af[3][4];
            #pragma unroll
            for (int la = 0; la < 3; la++)
                LDSM4(af[la], aoff + la*16384 + ((ks*32 + h16A) ^ axor));
            #pragma unroll
            for (int j = 0; j < 4; j++) {
                #pragma unroll
                for (int lb = 0; lb < NB; lb++) {
                    uint32_t bf4[4];
                    LDSM4(bf4, boff + lb*8192 + j*2048 + ((ks*32 + h16B) ^ bxor));
                    const int lamax = (NB == 3) ? (3 - lb) : 3;
                    #pragma unroll
                    for (int la = 0; la < 3; la++) {
                        if (la < lamax) {
                            MMA16816(acc[2*j],   af[la], bf4[0], bf4[1]);
                            MMA16816(acc[2*j+1], af[la], bf4[2], bf4[3]);
                        }
                    }
                }
            }
        }
        __syncthreads();
    }
    const float* bnp = (br == 0) ? B0 : ((br == 1) ? B1 : B2);
    const int g4 = lane >> 2, tg = lane & 3;
    const int o0 = mo + wid*16 + g4, o1 = o0 + 8;
    float gm0 = bnp[o0], bt0 = bnp[Cout+o0], mu0 = bnp[2*Cout+o0], vr0 = bnp[3*Cout+o0];
    float s0 = gm0 * rsqrtf(vr0 + EPSF);
    float f0 = bt0 - mu0*s0 + (bias ? s0*bias[o0] : 0.f);
    float gm1 = bnp[o1], bt1 = bnp[Cout+o1], mu1 = bnp[2*Cout+o1], vr1 = bnp[3*Cout+o1];
    float s1 = gm1 * rsqrtf(vr1 + EPSF);
    float f1 = bt1 - mu1*s1 + (bias ? s1*bias[o1] : 0.f);
    float* Yb = Y + ((size_t)(br*40 + g)*Cout)*256;
    #pragma unroll
    for (int j = 0; j < 8; j++) {
        int col = no + j*8 + tg*2;
        float2 r0; r0.x = s0*acc[j][0] + f0; r0.y = s0*acc[j][1] + f0;
        *reinterpret_cast<float2*>(&Yb[(size_t)o0*256 + col]) = r0;
        float2 r1; r1.x = s1*acc[j][2] + f1; r1.y = s1*acc[j][3] + f1;
        *reinterpret_cast<float2*>(&Yb[(size_t)o1*256 + col]) = r1;
    }
}

// ---------------- TIM up-conv + bn1 + LIF1 -> 40-bit masks ------------------------------
__global__ void upconv_lif_kernel(const float* __restrict__ A, u64* __restrict__ M) {
    extern __shared__ __align__(16) float sm[];
    float* As  = sm;
    float* Wsm = sm + 9720;
    const int c = blockIdx.x, b = blockIdx.y, br = blockIdx.z;
    const float* Ab = A + (size_t)br * BR_STRIDE_A;
    const int tid = threadIdx.x;
    for (int i = tid; i < 10800; i += 256) Wsm[i] = g_WupT[i];
    for (int idx = tid; idx < 9720; idx += 256) {
        int t = idx / 972, q = idx % 972;
        int dc = q / 324, q2 = q % 324;
        int hh = q2 / 18, ww = q2 % 18;
        int cc = c - 1 + dc;
        float v = 0.f;
        if (cc >= 0 && cc < 256 && hh >= 1 && hh <= 16 && ww >= 1 && ww <= 16)
            v = Ab[((t*4 + b)*256 + cc)*256 + (hh-1)*16 + (ww-1)];
        As[idx] = v;
    }
    __syncthreads();
    const int h = tid >> 4, w = tid & 15;
    u64 acc[20];
    #pragma unroll
    for (int j = 0; j < 20; j++) acc[j] = 0ull;
    for (int t = 0; t < 10; t++) {
        const float* at = As + t*972 + h*18 + w;
        const u64* wt = reinterpret_cast<const u64*>(Wsm) + t*540;
        #pragma unroll
        for (int dc = 0; dc < 3; dc++)
            #pragma unroll
            for (int dh = 0; dh < 3; dh++)
                #pragma unroll
                for (int dw = 0; dw < 3; dw++) {
                    float a = at[dc*324 + dh*18 + dw];
                    u64 a2; PACK2(a2, a, a);
                    const ulonglong2* wp2 =
                        reinterpret_cast<const ulonglong2*>(wt + (dc*9 + dh*3 + dw)*20);
                    #pragma unroll
                    for (int j2 = 0; j2 < 10; j2++) {
                        ulonglong2 wv = wp2[j2];
                        FMA2(acc[2*j2  ], a2, wv.x);
                        FMA2(acc[2*j2+1], a2, wv.y);
                    }
                }
    }
    float av[40];
    #pragma unroll
    for (int p = 0; p < 20; p++) {
        float lo, hi; UNPACK2(lo, hi, acc[p]);
        av[2*p] = lo; av[2*p+1] = hi;
    }
    u64 mask = 0ull;
    #pragma unroll
    for (int q = 0; q < 4; q++) {
        float memv = 0.f;
        #pragma unroll
        for (int s = 0; s < 10; s++) {
            int j = 4*s + q;
            float x = g_bn1s[j]*av[j] + g_bn1o[j];
            memv += 0.5f*(x - memv);
            if (memv > 1.0f) { mask |= (1ull << j); memv = 0.f; }
        }
    }
    M[((size_t)(br*4 + b)*256 + c)*256 + tid] = mask;
}

// ---------------- TIM down-conv nibble-LUT + bn2 + LIF2 -> spike BITMASKS ---------------
__global__ void downconv_lif_kernel(const u64* __restrict__ Mg, const float* __restrict__ Wd_g,
                                    const float* __restrict__ bn2, unsigned* __restrict__ Bits) {
    const int c = blockIdx.x, b = blockIdx.y, br = blockIdx.z;
    const u64* Mb = Mg + (size_t)(br*4 + b)*65536;
    __shared__ __align__(16) u64 Ms[972];
    __shared__ float LUT[4320];
    __shared__ float s_sc[10], s_of[10];
    const int tid = threadIdx.x;
    for (int i = tid; i < 4320; i += 256) {
        int tap = i / 160, rem = i - tap*160;
        int t = rem >> 4, nib = rem & 15;
        float v = 0.f;
        if (nib & 1) v += Wd_g[t*108 +  0 + tap];
        if (nib & 2) v += Wd_g[t*108 + 27 + tap];
        if (nib & 4) v += Wd_g[t*108 + 54 + tap];
        if (nib & 8) v += Wd_g[t*108 + 81 + tap];
        LUT[i] = v;
    }
    if (tid < 10) {
        float gm = bn2[tid], bt = bn2[10+tid], mu = bn2[20+tid], vr = bn2[30+tid];
        float s = gm * rsqrtf(vr + EPSF);
        s_sc[tid] = s; s_of[tid] = bt - mu*s;
    }
    for (int i = tid; i < 972; i += 256) {
        int dc = i / 324, rem = i - dc*324;
        int hh = rem / 18, ww = rem - hh*18;
        int cc = c - 1 + dc;
        u64 m = 0ull;
        if (cc >= 0 && cc < 256 && hh >= 1 && hh <= 16 && ww >= 1 && ww <= 16)
            m = Mb[cc*256 + (hh-1)*16 + (ww-1)];
        Ms[i] = m;
    }
    __syncthreads();
    const int h = tid >> 4, w = tid & 15;
    float acc[10];
    #pragma unroll
    for (int t = 0; t < 10; t++) acc[t] = 0.f;
    #pragma unroll
    for (int dc = 0; dc < 3; dc++)
        #pragma unroll
        for (int dh = 0; dh < 3; dh++)
            #pragma unroll
            for (int dw = 0; dw < 3; dw++) {
                u64 m = Ms[dc*324 + (h+dh)*18 + (w+dw)];
                unsigned mlo = (unsigned)m, mhi = (unsigned)(m >> 32);
                const float* lt = LUT + (dc*9 + dh*3 + dw)*160;
                #pragma unroll
                for (int t = 0; t < 8; t++)
                    acc[t] += lt[t*16 + ((mlo >> (4*t)) & 15u)];
                acc[8] += lt[128 + (mhi & 15u)];
                acc[9] += lt[144 + ((mhi >> 4) & 15u)];
            }
    const int wid = tid >> 5, lane = tid & 31;
    float memv = 0.f;
    #pragma unroll
    for (int t = 0; t < 10; t++) {
        float x = s_sc[t]*acc[t] + s_of[t];
        memv += 0.5f*(x - memv);
        float sp = memv > 1.0f ? 1.f : 0.f;
        unsigned blt = __ballot_sync(0xffffffffu, sp > 0.f);
        if (lane == 0)
            Bits[br*81920 + ((t*4 + b)*256 + c)*8 + wid] = blt;
        if (sp > 0.f) memv = 0.f;
    }
}

// ---------------- attention via bit ops: G = K^T V by popc, o = Q G (exact) -------------
__global__ void attn_kernel(const unsigned* __restrict__ Bits, float* __restrict__ Op) {
    const int hh = blockIdx.x, b = blockIdx.y, t = blockIdx.z;
    __shared__ unsigned Qsb[16][8], Ksb[16][8], Vsb[16][8];
    __shared__ __align__(16) float Gs[16][16];
    const int tid = threadIdx.x;
    const int gbase = ((t*4 + b)*256 + hh*16)*8;
    if (tid < 128) {
        int d = tid >> 3, w = tid & 7;
        Qsb[d][w] = Bits[gbase + d*8 + w];
        Ksb[d][w] = Bits[81920 + gbase + d*8 + w];
    } else {
        int r = tid - 128;
        int d = r >> 3, w = r & 7;
        Vsb[d][w] = Bits[163840 + gbase + d*8 + w];
    }
    __syncthreads();
    {
        int d1 = tid >> 4, d2 = tid & 15;
        unsigned s = 0;
        #pragma unroll
        for (int w = 0; w < 8; w++)
            s += __popc(Ksb[d1][w] & Vsb[d2][w]);
        Gs[d1][d2] = (float)s;
    }
    __syncthreads();
    const int n = tid;
    const int word = n >> 5;
    const unsigned bit = 1u << (n & 31);
    u64 one2; PACK2(one2, 1.0f, 1.0f);
    u64 acc2[8];
    #pragma unroll
    for (int i = 0; i < 8; i++) acc2[i] = 0ull;
    #pragma unroll
    for (int d1 = 0; d1 < 16; d1++) {
        if (Qsb[d1][word] & bit) {
            const u64* gp = reinterpret_cast<const u64*>(&Gs[d1][0]);
            #pragma unroll
            for (int i = 0; i < 8; i++) FMA2(acc2[i], one2, gp[i]);
        }
    }
    const int base = (t*4 + b)*65536 + hh*4096;
    #pragma unroll
    for (int i = 0; i < 8; i++) {
        float lo, hi; UNPACK2(lo, hi, acc2[i]);
        Op[base + (2*i  )*256 + n] = 0.25f*lo;
        Op[base + (2*i+1)*256 + n] = 0.25f*hi;
    }
}

// ---------------- float LIF over t ------------------------------------------------------
__global__ void lif_std_kernel(const float* __restrict__ in, float* __restrict__ out,
                               const float* __restrict__ res, int Cch, float vth) {
    int idx = blockIdx.x*256 + threadIdx.x;
    int per_b = Cch*256;
    int b = idx / per_b, cn = idx - b*per_b;
    float mem = 0.f;
    #pragma unroll
    for (int t = 0; t < 10; t++) {
        int off = (t*4 + b)*per_b + cn;
        float x = in[off];
        mem += 0.5f*(x - mem);
        float sp = mem > vth ? 1.f : 0.f;
        out[off] = res ? res[off] + sp : sp;
        if (sp > 0.f) mem = 0.f;
    }
}

// ---------------- launch ----------------
extern "C" void kernel_launch(void* const* d_in, const int* in_sizes, int n_in,
                              void* d_out, int out_size) {
    const float* x        = (const float*)d_in[0];
    const float* q_w      = (const float*)d_in[1];
    const float* q_bn     = (const float*)d_in[2];
    const float* k_w      = (const float*)d_in[3];
    const float* k_bn     = (const float*)d_in[4];
    const float* v_w      = (const float*)d_in[5];
    const float* v_bn     = (const float*)d_in[6];
    const float* proj_w   = (const float*)d_in[7];
    const float* proj_bn  = (const float*)d_in[8];
    const float* tim_up_w = (const float*)d_in[9];
    const float* tim_bn1  = (const float*)d_in[10];
    const float* tim_dn_w = (const float*)d_in[11];
    const float* tim_bn2  = (const float*)d_in[12];
    const float* fc1_w    = (const float*)d_in[13];
    const float* fc1_b    = (const float*)d_in[14];
    const float* fc1_bn   = (const float*)d_in[15];
    const float* fc2_w    = (const float*)d_in[16];
    const float* fc2_b    = (const float*)d_in[17];
    const float* fc2_bn   = (const float*)d_in[18];
    float* out = (float*)d_out;

    float *bA,*bO,*bP,*bH,*bF1,*bF2;
    u64 *bM;
    unsigned *bQKVb;
    bf16 *bXh,*bXm,*bXl,*bHh,*bHm,*bHl,*bSpOt,*bS2t;
    bf16 *wqh,*wqm,*wql,*wph,*wpm,*wpl,*w1h,*w1m,*w1l,*w2h,*w2m,*w2l;
    cudaGetSymbolAddress((void**)&bA,    g_A);
    cudaGetSymbolAddress((void**)&bM,    g_M);
    cudaGetSymbolAddress((void**)&bQKVb, g_QKVb);
    cudaGetSymbolAddress((void**)&bO,    g_O);
    cudaGetSymbolAddress((void**)&bP,    g_P);
    cudaGetSymbolAddress((void**)&bH,    g_H);
    cudaGetSymbolAddress((void**)&bF1,   g_F1);
    cudaGetSymbolAddress((void**)&bF2,   g_F2);
    cudaGetSymbolAddress((void**)&bXh, g_Xt_h); cudaGetSymbolAddress((void**)&bXm, g_Xt_m);
    cudaGetSymbolAddress((void**)&bXl, g_Xt_l);
    cudaGetSymbolAddress((void**)&bHh, g_Ht_h); cudaGetSymbolAddress((void**)&bHm, g_Ht_m);
    cudaGetSymbolAddress((void**)&bHl, g_Ht_l);
    cudaGetSymbolAddress((void**)&bSpOt, g_SpOt);
    cudaGetSymbolAddress((void**)&bS2t,  g_S2t);
    cudaGetSymbolAddress((void**)&wqh, g_Wq_h); cudaGetSymbolAddress((void**)&wqm, g_Wq_m);
    cudaGetSymbolAddress((void**)&wql, g_Wq_l);
    cudaGetSymbolAddress((void**)&wph, g_Wp_h); cudaGetSymbolAddress((void**)&wpm, g_Wp_m);
    cudaGetSymbolAddress((void**)&wpl, g_Wp_l);
    cudaGetSymbolAddress((void**)&w1h, g_W1_h); cudaGetSymbolAddress((void**)&w1m, g_W1_m);
    cudaGetSymbolAddress((void**)&w1l, g_W1_l);
    cudaGetSymbolAddress((void**)&w2h, g_W2_h); cudaGetSymbolAddress((void**)&w2m, g_W2_m);
    cudaGetSymbolAddress((void**)&w2l, g_W2_l);

    const int SM6 = 73728;   // A 48KB + B 24KB
    const int SM1 = 57344;   // A 48KB + B 8KB
    cudaFuncSetAttribute(upconv_lif_kernel, cudaFuncAttributeMaxDynamicSharedMemorySize, 82080);
    cudaFuncSetAttribute(gemm_mma_kernel<256,3>,  cudaFuncAttributeMaxDynamicSharedMemorySize, SM6);
    cudaFuncSetAttribute(gemm_mma_kernel<256,1>,  cudaFuncAttributeMaxDynamicSharedMemorySize, SM1);
    cudaFuncSetAttribute(gemm_mma_kernel<1024,1>, cudaFuncAttributeMaxDynamicSharedMemorySize, SM1);

    prep_kernel<<<43, 256>>>(tim_up_w, tim_bn1);
    prep_w_kernel<<<3072, 256>>>(q_w, k_w, v_w, proj_w, fc1_w, fc2_w);

    // --- qkv (mma.sync) -> TIM pipeline -> spike bitmasks ---
    cvt_xt_kernel<<<dim3(8,8,40), 256>>>(x, bXh, bXm, bXl);
    gemm_mma_kernel<256,3><<<dim3(4,2,120), 256, SM6>>>(
        bXh, bXm, bXl, wqh, wqm, wql, q_bn, k_bn, v_bn, nullptr, bA, 256);
    upconv_lif_kernel<<<dim3(256,4,3), 256, 82080>>>(bA, bM);
    downconv_lif_kernel<<<dim3(256,4,3), 256>>>(bM, tim_dn_w, tim_bn2, bQKVb);

    // --- attention (popc, exact) + attn-LIF (binary bf16 transposed) ---
    attn_kernel<<<dim3(16,4,10), 256>>>(bQKVb, bO);
    lif_t_bf16_kernel<<<dim3(8,8,4), 256>>>(bO, bSpOt, 256, 0.5f);

    // --- proj (binary X) + residual ---
    gemm_mma_kernel<256,1><<<dim3(4,2,40), 256, SM1>>>(
        bSpOt, nullptr, nullptr, wph, wpm, wpl, proj_bn, proj_bn, proj_bn, nullptr, bP, 256);
    lif_std_kernel<<<1024, 256>>>(bP, bH, x, 256, 1.0f);

    // --- mlp ---
    cvt_xt_kernel<<<dim3(8,8,40), 256>>>(bH, bHh, bHm, bHl);
    gemm_mma_kernel<256,3><<<dim3(4,8,40), 256, SM6>>>(
        bHh, bHm, bHl, w1h, w1m, w1l, fc1_bn, fc1_bn, fc1_bn, fc1_b, bF1, 1024);
    lif_t_bf16_kernel<<<dim3(32,8,4), 256>>>(bF1, bS2t, 1024, 1.0f);
    gemm_mma_kernel<1024,1><<<dim3(4,2,40), 256, SM1>>>(
        bS2t, nullptr, nullptr, w2h, w2m, w2l, fc2_bn, fc2_bn, fc2_bn, fc2_b, bF2, 256);
    lif_std_kernel<<<1024, 256>>>(bF2, out, bH, 256, 1.0f);
}

// round 17
// speedup vs baseline: 1.0546x; 1.0304x over previous
#include <cuda_runtime.h>
#include <cuda_bf16.h>
#include <cstdint>

#define TT 10
#define BB 4
#define CCH 256
#define NPIX 256
#define HIDN 1024
#define TRJ 40
#define EPSF 1e-5f

typedef unsigned long long u64;
typedef __nv_bfloat16 bf16;

#define FMA2(d,a,b)    asm("fma.rn.f32x2 %0, %1, %2, %0;" : "+l"(d) : "l"(a), "l"(b))
#define PACK2(d,lo,hi) asm("mov.b64 %0, {%1, %2};" : "=l"(d) : "f"(lo), "f"(hi))
#define UNPACK2(lo,hi,s) asm("mov.b64 {%0, %1}, %2;" : "=f"(lo), "=f"(hi) : "l"(s))

#define BR_STRIDE_A  2621440

// ---------------- mma.sync + cp.async helpers (sm_80+ PTX on sm_103 target) ------------
__device__ __forceinline__ uint32_t smem_to_u32(const void* p) {
    uint32_t a;
    asm("{ .reg .u64 t; cvta.to.shared.u64 t, %1; cvt.u32.u64 %0, t; }" : "=r"(a) : "l"(p));
    return a;
}
#define LDSM4(r, addr) \
    asm volatile("ldmatrix.sync.aligned.m8n8.x4.shared.b16 {%0,%1,%2,%3}, [%4];" \
        : "=r"((r)[0]), "=r"((r)[1]), "=r"((r)[2]), "=r"((r)[3]) : "r"(addr))
#define MMA16816(c, a, b0v, b1v) \
    asm volatile("mma.sync.aligned.m16n8k16.row.col.f32.bf16.bf16.f32 " \
        "{%0,%1,%2,%3}, {%4,%5,%6,%7}, {%8,%9}, {%0,%1,%2,%3};" \
        : "+f"((c)[0]), "+f"((c)[1]), "+f"((c)[2]), "+f"((c)[3]) \
        : "r"((a)[0]), "r"((a)[1]), "r"((a)[2]), "r"((a)[3]), "r"(b0v), "r"(b1v))
#define CPA16(sa, gp) \
    asm volatile("cp.async.ca.shared.global [%0], [%1], 16;" :: "r"(sa), "l"(gp) : "memory")
#define CPA_COMMIT() asm volatile("cp.async.commit_group;" ::: "memory")
#define CPA_WAIT1()  asm volatile("cp.async.wait_group 1;" ::: "memory")
#define CPA_WAIT0()  asm volatile("cp.async.wait_group 0;" ::: "memory")

// ---------------- scratch ----------------
__device__ float g_A  [3*TT*BB*CCH*NPIX];
__device__ u64   g_M  [3*BB*CCH*NPIX];
__device__ unsigned g_QKVb[3*TT*BB*CCH*8];   // spike bitmasks [br][(t*4+b)][c][w]
__device__ float g_O  [TT*BB*CCH*NPIX];
__device__ float g_P  [TT*BB*CCH*NPIX];
__device__ float g_H  [TT*BB*CCH*NPIX];
__device__ float g_F1 [TT*BB*HIDN*NPIX];
__device__ float g_F2 [TT*BB*CCH*NPIX];
__device__ float g_WupT[270*40];
__device__ float g_bn1s[40], g_bn1o[40];
// bf16 limbs
__device__ bf16 g_Wq_h[196608], g_Wq_m[196608], g_Wq_l[196608];
__device__ bf16 g_Wp_h[65536],  g_Wp_m[65536],  g_Wp_l[65536];
__device__ bf16 g_W1_h[262144], g_W1_m[262144], g_W1_l[262144];
__device__ bf16 g_W2_h[262144], g_W2_m[262144], g_W2_l[262144];
__device__ bf16 g_Xt_h[2621440], g_Xt_m[2621440], g_Xt_l[2621440];
__device__ bf16 g_Ht_h[2621440], g_Ht_m[2621440], g_Ht_l[2621440];
__device__ bf16 g_SpOt[2621440];     // binary, [g][n][256]
__device__ bf16 g_S2t[10485760];     // binary, [g][n][1024]

__device__ __forceinline__ void split3(float v, bf16& h, bf16& m, bf16& l) {
    h = __float2bfloat16(v);
    float r1 = v - __bfloat162float(h);
    m = __float2bfloat16(r1);
    l = __float2bfloat16(r1 - __bfloat162float(m));
}

// ---------------- prep ----------------
__global__ void prep_kernel(const float* __restrict__ up_w, const float* __restrict__ bn1) {
    for (int idx = blockIdx.x*blockDim.x + threadIdx.x; idx < 10800;
         idx += gridDim.x*blockDim.x) {
        int j = idx / 270, r = idx % 270;
        g_WupT[r*40 + j] = up_w[idx];
    }
    int i = blockIdx.x*blockDim.x + threadIdx.x;
    if (i < 40) {
        float gm = bn1[i], bt = bn1[40+i], mu = bn1[80+i], vr = bn1[120+i];
        float s = gm * rsqrtf(vr + EPSF);
        g_bn1s[i] = s; g_bn1o[i] = bt - mu*s;
    }
}

__global__ void prep_w_kernel(const float* __restrict__ q_w, const float* __restrict__ k_w,
                              const float* __restrict__ v_w, const float* __restrict__ proj_w,
                              const float* __restrict__ fc1_w, const float* __restrict__ fc2_w) {
    int i = blockIdx.x*256 + threadIdx.x;
    if (i >= 786432) return;
    float v; bf16 *dh, *dm, *dl; int o;
    if (i < 196608) {
        int br = i >> 16;
        const float* w = (br == 0) ? q_w : ((br == 1) ? k_w : v_w);
        v = w[i & 65535]; o = i; dh = g_Wq_h; dm = g_Wq_m; dl = g_Wq_l;
    } else if (i < 262144) {
        o = i - 196608; v = proj_w[o]; dh = g_Wp_h; dm = g_Wp_m; dl = g_Wp_l;
    } else if (i < 524288) {
        o = i - 262144; v = fc1_w[o]; dh = g_W1_h; dm = g_W1_m; dl = g_W1_l;
    } else {
        o = i - 524288; v = fc2_w[o]; dh = g_W2_h; dm = g_W2_m; dl = g_W2_l;
    }
    bf16 h, m, l; split3(v, h, m, l);
    dh[o] = h; dm[o] = m; dl[o] = l;
}

// float [g][256][256] -> transposed 3-limb bf16 [g][n][256]
__global__ void cvt_xt_kernel(const float* __restrict__ X, bf16* __restrict__ Xh,
                              bf16* __restrict__ Xm, bf16* __restrict__ Xl) {
    __shared__ float s[32][33];
    const int c0 = blockIdx.x*32, n0 = blockIdx.y*32, g = blockIdx.z;
    const int tid = threadIdx.x;
    #pragma unroll
    for (int it = 0; it < 4; it++) {
        int c = (tid>>5) + it*8;
        s[c][tid&31] = X[((size_t)g*256 + c0+c)*256 + n0 + (tid&31)];
    }
    __syncthreads();
    const int cc = tid & 31;
    #pragma unroll
    for (int it = 0; it < 4; it++) {
        int nn = (tid>>5) + it*8;
        bf16 h, m, l; split3(s[cc][nn], h, m, l);
        size_t o = ((size_t)g*256 + n0+nn)*256 + c0+cc;
        Xh[o] = h; Xm[o] = m; Xl[o] = l;
    }
}

// LIF over t + transpose to binary bf16 [g][n][C]
__global__ void lif_t_bf16_kernel(const float* __restrict__ in, bf16* __restrict__ out,
                                  int C, float vth) {
    __shared__ float s[10][32][33];
    const int c0 = blockIdx.x*32, n0 = blockIdx.y*32, b = blockIdx.z;
    const int tid = threadIdx.x;
    for (int t = 0; t < 10; t++)
        #pragma unroll
        for (int it = 0; it < 4; it++) {
            int c = (tid>>5) + it*8;
            s[t][c][tid&31] = in[((size_t)(t*4+b)*C + c0+c)*256 + n0 + (tid&31)];
        }
    __syncthreads();
    const int cc = tid & 31;
    #pragma unroll
    for (int pass = 0; pass < 4; pass++) {
        int nn = (tid>>5) + pass*8;
        float memv = 0.f;
        #pragma unroll
        for (int t = 0; t < 10; t++) {
            float x = s[t][cc][nn];
            memv += 0.5f*(x - memv);
            float sp = memv > vth ? 1.f : 0.f;
            out[((size_t)(t*4+b)*256 + n0+nn)*C + c0+cc] = __float2bfloat16(sp);
            if (sp > 0.f) memv = 0.f;
        }
    }
}

// ---------------- mma.sync GEMM + BN(+bias), limb-decomposed, cp.async double-buffer ---
// D[mo+m][no+n] = sum_k W[m][k]*X[n][k]. M=128 N=64, K chunks of 64, 8 warps, 2 stages.
template<int CIN, int NB>
__global__ void __launch_bounds__(256, 1) gemm_mma_kernel(
        const bf16* __restrict__ Xh, const bf16* __restrict__ Xm, const bf16* __restrict__ Xl,
        const bf16* __restrict__ Wh, const bf16* __restrict__ Wm, const bf16* __restrict__ Wl,
        const float* __restrict__ B0, const float* __restrict__ B1, const float* __restrict__ B2,
        const float* __restrict__ bias, float* __restrict__ Y, int Cout) {
    extern __shared__ char dsm[];
    constexpr int BSZ = NB*8192;
    constexpr int STG = 49152 + BSZ;        // stage size: A 48KB + B NB*8KB
    const int z = blockIdx.z, br = z/40, g = z - br*40;
    const int mo = blockIdx.y*128, no = blockIdx.x*64;
    const int tid = threadIdx.x, wid = tid>>5, lane = tid&31;
    const bf16* Wp[3] = {Wh + (size_t)br*Cout*CIN, Wm + (size_t)br*Cout*CIN,
                         Wl + (size_t)br*Cout*CIN};
    const bf16* Xp[3];
    Xp[0] = Xh + (size_t)g*256*CIN;
    Xp[1] = (NB > 1) ? Xm + (size_t)g*256*CIN : Xp[0];
    Xp[2] = (NB > 1) ? Xl + (size_t)g*256*CIN : Xp[0];

    float acc[8][4];
    #pragma unroll
    for (int j = 0; j < 8; j++)
        #pragma unroll
        for (int i = 0; i < 4; i++) acc[j][i] = 0.f;

    const uint32_t sbase = smem_to_u32(dsm);
    const int rowA = wid*16 + (lane & 7) + ((lane & 8) ? 8 : 0);
    const int h16A = (lane & 16) ? 16 : 0;
    const int axor = (rowA & 7)*16;
    const int rB = (lane & 7) + ((lane & 16) ? 8 : 0);
    const int h16B = (lane & 8) ? 16 : 0;
    const int bxor = (lane & 7)*16;

    // per-thread fill coordinates (A: 4 rows x 1 col16; B: per limb 2 rows)
    const int frA = tid >> 3, fcA = tid & 7;        // A row (per 256-step), col16
    const uint32_t fsA = frA*128 + ((fcA*16) ^ ((frA & 7)*16));
    const int NCH = CIN/64;

    // issue cp.async fills for chunk ch into stage stg
    auto issue = [&](int ch, int stg) {
        const uint32_t sb = sbase + stg*STG;
        #pragma unroll
        for (int it = 0; it < 4; it++) {       // A rows frA + it*32, 3 limbs
            int row = frA + it*32;
            uint32_t sa = sb + row*128 + ((fcA*16) ^ ((row & 7)*16));
            #pragma unroll
            for (int l = 0; l < 3; l++)
                CPA16(sa + l*16384,
                      &Wp[l][(size_t)(mo+row)*CIN + ch*64 + fcA*8]);
        }
        #pragma unroll
        for (int it = 0; it < 2; it++) {       // B rows frA + it*32, NB limbs
            int row = frA + it*32;
            uint32_t sa = sb + 49152 + row*128 + ((fcA*16) ^ ((row & 7)*16));
            #pragma unroll
            for (int l = 0; l < NB; l++)
                CPA16(sa + l*8192,
                      &Xp[l][(size_t)(no+row)*CIN + ch*64 + fcA*8]);
        }
        CPA_COMMIT();
    };

    issue(0, 0);
    for (int ch = 0; ch < NCH; ch++) {
        if (ch + 1 < NCH) { issue(ch+1, (ch+1) & 1); CPA_WAIT1(); }
        else              { CPA_WAIT0(); }
        __syncthreads();
        const uint32_t aoff = sbase + (ch & 1)*STG + rowA*128;
        const uint32_t boff = sbase + (ch & 1)*STG + 49152 + rB*128;
        #pragma unroll
        for (int ks = 0; ks < 4; ks++) {
            uint32_t af[3][4];
            #pragma unroll
            for (int la = 0; la < 3; la++)
                LDSM4(af[la], aoff + la*16384 + ((ks*32 + h16A) ^ axor));
            #pragma unroll
            for (int j = 0; j < 4; j++) {
                #pragma unroll
                for (int lb = 0; lb < NB; lb++) {
                    uint32_t bf4[4];
                    LDSM4(bf4, boff + lb*8192 + j*2048 + ((ks*32 + h16B) ^ bxor));
                    const int lamax = (NB == 3) ? (3 - lb) : 3;
                    #pragma unroll
                    for (int la = 0; la < 3; la++) {
                        if (la < lamax) {
                            MMA16816(acc[2*j],   af[la], bf4[0], bf4[1]);
                            MMA16816(acc[2*j+1], af[la], bf4[2], bf4[3]);
                        }
                    }
                }
            }
        }
        __syncthreads();
    }
    const float* bnp = (br == 0) ? B0 : ((br == 1) ? B1 : B2);
    const int g4 = lane >> 2, tg = lane & 3;
    const int o0 = mo + wid*16 + g4, o1 = o0 + 8;
    float gm0 = bnp[o0], bt0 = bnp[Cout+o0], mu0 = bnp[2*Cout+o0], vr0 = bnp[3*Cout+o0];
    float s0 = gm0 * rsqrtf(vr0 + EPSF);
    float f0 = bt0 - mu0*s0 + (bias ? s0*bias[o0] : 0.f);
    float gm1 = bnp[o1], bt1 = bnp[Cout+o1], mu1 = bnp[2*Cout+o1], vr1 = bnp[3*Cout+o1];
    float s1 = gm1 * rsqrtf(vr1 + EPSF);
    float f1 = bt1 - mu1*s1 + (bias ? s1*bias[o1] : 0.f);
    float* Yb = Y + ((size_t)(br*40 + g)*Cout)*256;
    #pragma unroll
    for (int j = 0; j < 8; j++) {
        int col = no + j*8 + tg*2;
        float2 r0; r0.x = s0*acc[j][0] + f0; r0.y = s0*acc[j][1] + f0;
        *reinterpret_cast<float2*>(&Yb[(size_t)o0*256 + col]) = r0;
        float2 r1; r1.x = s1*acc[j][2] + f1; r1.y = s1*acc[j][3] + f1;
        *reinterpret_cast<float2*>(&Yb[(size_t)o1*256 + col]) = r1;
    }
}

// ---------------- TIM up-conv + bn1 + LIF1 -> 40-bit masks ------------------------------
__global__ void upconv_lif_kernel(const float* __restrict__ A, u64* __restrict__ M) {
    extern __shared__ __align__(16) float sm[];
    float* As  = sm;
    float* Wsm = sm + 9720;
    const int c = blockIdx.x, b = blockIdx.y, br = blockIdx.z;
    const float* Ab = A + (size_t)br * BR_STRIDE_A;
    const int tid = threadIdx.x;
    for (int i = tid; i < 10800; i += 256) Wsm[i] = g_WupT[i];
    for (int idx = tid; idx < 9720; idx += 256) {
        int t = idx / 972, q = idx % 972;
        int dc = q / 324, q2 = q % 324;
        int hh = q2 / 18, ww = q2 % 18;
        int cc = c - 1 + dc;
        float v = 0.f;
        if (cc >= 0 && cc < 256 && hh >= 1 && hh <= 16 && ww >= 1 && ww <= 16)
            v = Ab[((t*4 + b)*256 + cc)*256 + (hh-1)*16 + (ww-1)];
        As[idx] = v;
    }
    __syncthreads();
    const int h = tid >> 4, w = tid & 15;
    u64 acc[20];
    #pragma unroll
    for (int j = 0; j < 20; j++) acc[j] = 0ull;
    for (int t = 0; t < 10; t++) {
        const float* at = As + t*972 + h*18 + w;
        const u64* wt = reinterpret_cast<const u64*>(Wsm) + t*540;
        #pragma unroll
        for (int dc = 0; dc < 3; dc++)
            #pragma unroll
            for (int dh = 0; dh < 3; dh++)
                #pragma unroll
                for (int dw = 0; dw < 3; dw++) {
                    float a = at[dc*324 + dh*18 + dw];
                    u64 a2; PACK2(a2, a, a);
                    const ulonglong2* wp2 =
                        reinterpret_cast<const ulonglong2*>(wt + (dc*9 + dh*3 + dw)*20);
                    #pragma unroll
                    for (int j2 = 0; j2 < 10; j2++) {
                        ulonglong2 wv = wp2[j2];
                        FMA2(acc[2*j2  ], a2, wv.x);
                        FMA2(acc[2*j2+1], a2, wv.y);
                    }
                }
    }
    float av[40];
    #pragma unroll
    for (int p = 0; p < 20; p++) {
        float lo, hi; UNPACK2(lo, hi, acc[p]);
        av[2*p] = lo; av[2*p+1] = hi;
    }
    u64 mask = 0ull;
    #pragma unroll
    for (int q = 0; q < 4; q++) {
        float memv = 0.f;
        #pragma unroll
        for (int s = 0; s < 10; s++) {
            int j = 4*s + q;
            float x = g_bn1s[j]*av[j] + g_bn1o[j];
            memv += 0.5f*(x - memv);
            if (memv > 1.0f) { mask |= (1ull << j); memv = 0.f; }
        }
    }
    M[((size_t)(br*4 + b)*256 + c)*256 + tid] = mask;
}

// ---------------- TIM down-conv nibble-LUT + bn2 + LIF2 -> spike BITMASKS ---------------
__global__ void downconv_lif_kernel(const u64* __restrict__ Mg, const float* __restrict__ Wd_g,
                                    const float* __restrict__ bn2, unsigned* __restrict__ Bits) {
    const int c = blockIdx.x, b = blockIdx.y, br = blockIdx.z;
    const u64* Mb = Mg + (size_t)(br*4 + b)*65536;
    __shared__ __align__(16) u64 Ms[972];
    __shared__ float LUT[4320];
    __shared__ float s_sc[10], s_of[10];
    const int tid = threadIdx.x;
    for (int i = tid; i < 4320; i += 256) {
        int tap = i / 160, rem = i - tap*160;
        int t = rem >> 4, nib = rem & 15;
        float v = 0.f;
        if (nib & 1) v += Wd_g[t*108 +  0 + tap];
        if (nib & 2) v += Wd_g[t*108 + 27 + tap];
        if (nib & 4) v += Wd_g[t*108 + 54 + tap];
        if (nib & 8) v += Wd_g[t*108 + 81 + tap];
        LUT[i] = v;
    }
    if (tid < 10) {
        float gm = bn2[tid], bt = bn2[10+tid], mu = bn2[20+tid], vr = bn2[30+tid];
        float s = gm * rsqrtf(vr + EPSF);
        s_sc[tid] = s; s_of[tid] = bt - mu*s;
    }
    for (int i = tid; i < 972; i += 256) {
        int dc = i / 324, rem = i - dc*324;
        int hh = rem / 18, ww = rem - hh*18;
        int cc = c - 1 + dc;
        u64 m = 0ull;
        if (cc >= 0 && cc < 256 && hh >= 1 && hh <= 16 && ww >= 1 && ww <= 16)
            m = Mb[cc*256 + (hh-1)*16 + (ww-1)];
        Ms[i] = m;
    }
    __syncthreads();
    const int h = tid >> 4, w = tid & 15;
    float acc[10];
    #pragma unroll
    for (int t = 0; t < 10; t++) acc[t] = 0.f;
    #pragma unroll
    for (int dc = 0; dc < 3; dc++)
        #pragma unroll
        for (int dh = 0; dh < 3; dh++)
            #pragma unroll
            for (int dw = 0; dw < 3; dw++) {
                u64 m = Ms[dc*324 + (h+dh)*18 + (w+dw)];
                unsigned mlo = (unsigned)m, mhi = (unsigned)(m >> 32);
                const float* lt = LUT + (dc*9 + dh*3 + dw)*160;
                #pragma unroll
                for (int t = 0; t < 8; t++)
                    acc[t] += lt[t*16 + ((mlo >> (4*t)) & 15u)];
                acc[8] += lt[128 + (mhi & 15u)];
                acc[9] += lt[144 + ((mhi >> 4) & 15u)];
            }
    const int wid = tid >> 5, lane = tid & 31;
    float memv = 0.f;
    #pragma unroll
    for (int t = 0; t < 10; t++) {
        float x = s_sc[t]*acc[t] + s_of[t];
        memv += 0.5f*(x - memv);
        float sp = memv > 1.0f ? 1.f : 0.f;
        unsigned blt = __ballot_sync(0xffffffffu, sp > 0.f);
        if (lane == 0)
            Bits[br*81920 + ((t*4 + b)*256 + c)*8 + wid] = blt;
        if (sp > 0.f) memv = 0.f;
    }
}

// ---------------- attention via bit ops: G = K^T V by popc, o = Q G (exact) -------------
__global__ void attn_kernel(const unsigned* __restrict__ Bits, float* __restrict__ Op) {
    const int hh = blockIdx.x, b = blockIdx.y, t = blockIdx.z;
    __shared__ unsigned Qsb[16][8], Ksb[16][8], Vsb[16][8];
    __shared__ __align__(16) float Gs[16][16];
    const int tid = threadIdx.x;
    const int gbase = ((t*4 + b)*256 + hh*16)*8;
    if (tid < 128) {
        int d = tid >> 3, w = tid & 7;
        Qsb[d][w] = Bits[gbase + d*8 + w];
        Ksb[d][w] = Bits[81920 + gbase + d*8 + w];
    } else {
        int r = tid - 128;
        int d = r >> 3, w = r & 7;
        Vsb[d][w] = Bits[163840 + gbase + d*8 + w];
    }
    __syncthreads();
    {
        int d1 = tid >> 4, d2 = tid & 15;
        unsigned s = 0;
        #pragma unroll
        for (int w = 0; w < 8; w++)
            s += __popc(Ksb[d1][w] & Vsb[d2][w]);
        Gs[d1][d2] = (float)s;
    }
    __syncthreads();
    const int n = tid;
    const int word = n >> 5;
    const unsigned bit = 1u << (n & 31);
    u64 one2; PACK2(one2, 1.0f, 1.0f);
    u64 acc2[8];
    #pragma unroll
    for (int i = 0; i < 8; i++) acc2[i] = 0ull;
    #pragma unroll
    for (int d1 = 0; d1 < 16; d1++) {
        if (Qsb[d1][word] & bit) {
            const u64* gp = reinterpret_cast<const u64*>(&Gs[d1][0]);
            #pragma unroll
            for (int i = 0; i < 8; i++) FMA2(acc2[i], one2, gp[i]);
        }
    }
    const int base = (t*4 + b)*65536 + hh*4096;
    #pragma unroll
    for (int i = 0; i < 8; i++) {
        float lo, hi; UNPACK2(lo, hi, acc2[i]);
        Op[base + (2*i  )*256 + n] = 0.25f*lo;
        Op[base + (2*i+1)*256 + n] = 0.25f*hi;
    }
}

// ---------------- float LIF over t ------------------------------------------------------
__global__ void lif_std_kernel(const float* __restrict__ in, float* __restrict__ out,
                               const float* __restrict__ res, int Cch, float vth) {
    int idx = blockIdx.x*256 + threadIdx.x;
    int per_b = Cch*256;
    int b = idx / per_b, cn = idx - b*per_b;
    float mem = 0.f;
    #pragma unroll
    for (int t = 0; t < 10; t++) {
        int off = (t*4 + b)*per_b + cn;
        float x = in[off];
        mem += 0.5f*(x - mem);
        float sp = mem > vth ? 1.f : 0.f;
        out[off] = res ? res[off] + sp : sp;
        if (sp > 0.f) mem = 0.f;
    }
}

// ---------------- launch ----------------
extern "C" void kernel_launch(void* const* d_in, const int* in_sizes, int n_in,
                              void* d_out, int out_size) {
    const float* x        = (const float*)d_in[0];
    const float* q_w      = (const float*)d_in[1];
    const float* q_bn     = (const float*)d_in[2];
    const float* k_w      = (const float*)d_in[3];
    const float* k_bn     = (const float*)d_in[4];
    const float* v_w      = (const float*)d_in[5];
    const float* v_bn     = (const float*)d_in[6];
    const float* proj_w   = (const float*)d_in[7];
    const float* proj_bn  = (const float*)d_in[8];
    const float* tim_up_w = (const float*)d_in[9];
    const float* tim_bn1  = (const float*)d_in[10];
    const float* tim_dn_w = (const float*)d_in[11];
    const float* tim_bn2  = (const float*)d_in[12];
    const float* fc1_w    = (const float*)d_in[13];
    const float* fc1_b    = (const float*)d_in[14];
    const float* fc1_bn   = (const float*)d_in[15];
    const float* fc2_w    = (const float*)d_in[16];
    const float* fc2_b    = (const float*)d_in[17];
    const float* fc2_bn   = (const float*)d_in[18];
    float* out = (float*)d_out;

    float *bA,*bO,*bP,*bH,*bF1,*bF2;
    u64 *bM;
    unsigned *bQKVb;
    bf16 *bXh,*bXm,*bXl,*bHh,*bHm,*bHl,*bSpOt,*bS2t;
    bf16 *wqh,*wqm,*wql,*wph,*wpm,*wpl,*w1h,*w1m,*w1l,*w2h,*w2m,*w2l;
    cudaGetSymbolAddress((void**)&bA,    g_A);
    cudaGetSymbolAddress((void**)&bM,    g_M);
    cudaGetSymbolAddress((void**)&bQKVb, g_QKVb);
    cudaGetSymbolAddress((void**)&bO,    g_O);
    cudaGetSymbolAddress((void**)&bP,    g_P);
    cudaGetSymbolAddress((void**)&bH,    g_H);
    cudaGetSymbolAddress((void**)&bF1,   g_F1);
    cudaGetSymbolAddress((void**)&bF2,   g_F2);
    cudaGetSymbolAddress((void**)&bXh, g_Xt_h); cudaGetSymbolAddress((void**)&bXm, g_Xt_m);
    cudaGetSymbolAddress((void**)&bXl, g_Xt_l);
    cudaGetSymbolAddress((void**)&bHh, g_Ht_h); cudaGetSymbolAddress((void**)&bHm, g_Ht_m);
    cudaGetSymbolAddress((void**)&bHl, g_Ht_l);
    cudaGetSymbolAddress((void**)&bSpOt, g_SpOt);
    cudaGetSymbolAddress((void**)&bS2t,  g_S2t);
    cudaGetSymbolAddress((void**)&wqh, g_Wq_h); cudaGetSymbolAddress((void**)&wqm, g_Wq_m);
    cudaGetSymbolAddress((void**)&wql, g_Wq_l);
    cudaGetSymbolAddress((void**)&wph, g_Wp_h); cudaGetSymbolAddress((void**)&wpm, g_Wp_m);
    cudaGetSymbolAddress((void**)&wpl, g_Wp_l);
    cudaGetSymbolAddress((void**)&w1h, g_W1_h); cudaGetSymbolAddress((void**)&w1m, g_W1_m);
    cudaGetSymbolAddress((void**)&w1l, g_W1_l);
    cudaGetSymbolAddress((void**)&w2h, g_W2_h); cudaGetSymbolAddress((void**)&w2m, g_W2_m);
    cudaGetSymbolAddress((void**)&w2l, g_W2_l);

    const int SM6 = 2*(49152 + 24576);   // 147456: 2 stages of A 48KB + B 24KB
    const int SM1 = 2*(49152 + 8192);    // 114688: 2 stages of A 48KB + B 8KB
    cudaFuncSetAttribute(upconv_lif_kernel, cudaFuncAttributeMaxDynamicSharedMemorySize, 82080);
    cudaFuncSetAttribute(gemm_mma_kernel<256,3>,  cudaFuncAttributeMaxDynamicSharedMemorySize, SM6);
    cudaFuncSetAttribute(gemm_mma_kernel<256,1>,  cudaFuncAttributeMaxDynamicSharedMemorySize, SM1);
    cudaFuncSetAttribute(gemm_mma_kernel<1024,1>, cudaFuncAttributeMaxDynamicSharedMemorySize, SM1);

    prep_kernel<<<43, 256>>>(tim_up_w, tim_bn1);
    prep_w_kernel<<<3072, 256>>>(q_w, k_w, v_w, proj_w, fc1_w, fc2_w);

    // --- qkv (mma.sync) -> TIM pipeline -> spike bitmasks ---
    cvt_xt_kernel<<<dim3(8,8,40), 256>>>(x, bXh, bXm, bXl);
    gemm_mma_kernel<256,3><<<dim3(4,2,120), 256, SM6>>>(
        bXh, bXm, bXl, wqh, wqm, wql, q_bn, k_bn, v_bn, nullptr, bA, 256);
    upconv_lif_kernel<<<dim3(256,4,3), 256, 82080>>>(bA, bM);
    downconv_lif_kernel<<<dim3(256,4,3), 256>>>(bM, tim_dn_w, tim_bn2, bQKVb);

    // --- attention (popc, exact) + attn-LIF (binary bf16 transposed) ---
    attn_kernel<<<dim3(16,4,10), 256>>>(bQKVb, bO);
    lif_t_bf16_kernel<<<dim3(8,8,4), 256>>>(bO, bSpOt, 256, 0.5f);

    // --- proj (binary X) + residual ---
    gemm_mma_kernel<256,1><<<dim3(4,2,40), 256, SM1>>>(
        bSpOt, nullptr, nullptr, wph, wpm, wpl, proj_bn, proj_bn, proj_bn, nullptr, bP, 256);
    lif_std_kernel<<<1024, 256>>>(bP, bH, x, 256, 1.0f);

    // --- mlp ---
    cvt_xt_kernel<<<dim3(8,8,40), 256>>>(bH, bHh, bHm, bHl);
    gemm_mma_kernel<256,3><<<dim3(4,8,40), 256, SM6>>>(
        bHh, bHm, bHl, w1h, w1m, w1l, fc1_bn, fc1_bn, fc1_bn, fc1_b, bF1, 1024);
    lif_t_bf16_kernel<<<dim3(32,8,4), 256>>>(bF1, bS2t, 1024, 1.0f);
    gemm_mma_kernel<1024,1><<<dim3(4,2,40), 256, SM1>>>(
        bS2t, nullptr, nullptr, w2h, w2m, w2l, fc2_bn, fc2_bn, fc2_bn, fc2_b, bF2, 256);
    lif_std_kernel<<<1024, 256>>>(bF2, out, bH, 256, 1.0f);
}